// round 1
// baseline (speedup 1.0000x reference)
#include <cuda_runtime.h>
#include <math.h>

#define T 1024
#define H 2048
#define I_DIM 1024
#define E 32

#define BM 64
#define BN 64
#define BK 16

// Scratch (no allocations allowed -> __device__ globals)
__device__ int   g_count[E];
__device__ int   g_list[E * T];          // pair ids (t*2+k) grouped per expert
__device__ float g_pairw[T * 2];         // combine weight per (token, k) pair
__device__ float g_hbuf[(size_t)T * 2 * I_DIM];  // silu(g)*u*w, 8 MB

// ---------------------------------------------------------------------------
__global__ void zero_kernel(float* __restrict__ out) {
    int i = blockIdx.x * blockDim.x + threadIdx.x;
    if (i < T * H) out[i] = 0.0f;
    if (i < E) g_count[i] = 0;
}

// ---------------------------------------------------------------------------
// One block per token: 32 logits, top-2, normalized weights, scatter to lists.
__global__ __launch_bounds__(128) void router_kernel(
    const float* __restrict__ x, const float* __restrict__ gw) {
    int t = blockIdx.x;
    __shared__ float logits[E];
    int warp = threadIdx.x >> 5;
    int lane = threadIdx.x & 31;
    const float4* xt = (const float4*)(x + (size_t)t * H);

    for (int e = warp; e < E; e += 4) {
        const float4* w = (const float4*)(gw + (size_t)e * H);
        float s = 0.0f;
        #pragma unroll 4
        for (int h = lane; h < H / 4; h += 32) {
            float4 a = xt[h];
            float4 b = w[h];
            s += a.x * b.x + a.y * b.y + a.z * b.z + a.w * b.w;
        }
        #pragma unroll
        for (int o = 16; o; o >>= 1) s += __shfl_xor_sync(0xffffffffu, s, o);
        if (lane == 0) logits[e] = s;
    }
    __syncthreads();

    if (threadIdx.x == 0) {
        // top-2 scan; strict '>' keeps lowest index on ties (matches lax.top_k)
        float b1 = -1e30f, b2 = -1e30f;
        int i1 = 0, i2 = 0;
        #pragma unroll
        for (int e = 0; e < E; e++) {
            float v = logits[e];
            if (v > b1)      { b2 = b1; i2 = i1; b1 = v; i1 = e; }
            else if (v > b2) { b2 = v; i2 = e; }
        }
        // renormalized top-2 softmax weights: full-softmax denominator cancels
        float w1 = 1.0f / (1.0f + expf(b2 - b1));
        float w2 = 1.0f - w1;
        g_pairw[t * 2 + 0] = w1;
        g_pairw[t * 2 + 1] = w2;
        int p1 = atomicAdd(&g_count[i1], 1);
        g_list[i1 * T + p1] = t * 2 + 0;
        int p2 = atomicAdd(&g_count[i2], 1);
        g_list[i2 * T + p2] = t * 2 + 1;
    }
}

// ---------------------------------------------------------------------------
// Per-expert gathered SGEMM: [slots, H] x (Wg[e], Wu[e])^T -> fused SwiGLU.
// Block tile: BM slots x BN intermediate cols, K = H.
__global__ __launch_bounds__(256) void gateup_kernel(
    const float* __restrict__ x,
    const float* __restrict__ Wg,
    const float* __restrict__ Wu) {
    int e = blockIdx.z;
    int cnt = g_count[e];
    int slot0 = blockIdx.x * BM;
    if (slot0 >= cnt) return;
    int i0 = blockIdx.y * BN;

    __shared__ float As[BK][BM];
    __shared__ float Bgs[BK][BN];
    __shared__ float Bus[BK][BN];
    __shared__ int   spair[BM];

    int tid = threadIdx.x;
    if (tid < BM) {
        int s = slot0 + tid;
        spair[tid] = (s < cnt) ? g_list[e * T + s] : -1;
    }
    __syncthreads();

    int lr = tid >> 2;           // 0..63 : row within tile
    int lk = (tid & 3) << 2;     // 0,4,8,12 : k offset (float4)
    int pr = spair[lr];
    // invalid slots read token 0 (garbage columns are masked at store)
    const float* arow = x + (size_t)((pr >= 0) ? (pr >> 1) : 0) * H;
    const float* wg = Wg + ((size_t)e * I_DIM + i0 + lr) * H;
    const float* wu = Wu + ((size_t)e * I_DIM + i0 + lr) * H;

    int tx = tid & 15, ty = tid >> 4;
    float accg[4][4];
    float accu[4][4];
    #pragma unroll
    for (int i = 0; i < 4; i++)
        #pragma unroll
        for (int j = 0; j < 4; j++) { accg[i][j] = 0.0f; accu[i][j] = 0.0f; }

    for (int k0 = 0; k0 < H; k0 += BK) {
        float4 av = *(const float4*)(arow + k0 + lk);
        float4 gv = *(const float4*)(wg + k0 + lk);
        float4 uv = *(const float4*)(wu + k0 + lk);
        __syncthreads();
        As[lk + 0][lr] = av.x; As[lk + 1][lr] = av.y;
        As[lk + 2][lr] = av.z; As[lk + 3][lr] = av.w;
        Bgs[lk + 0][lr] = gv.x; Bgs[lk + 1][lr] = gv.y;
        Bgs[lk + 2][lr] = gv.z; Bgs[lk + 3][lr] = gv.w;
        Bus[lk + 0][lr] = uv.x; Bus[lk + 1][lr] = uv.y;
        Bus[lk + 2][lr] = uv.z; Bus[lk + 3][lr] = uv.w;
        __syncthreads();
        #pragma unroll
        for (int kk = 0; kk < BK; kk++) {
            float4 a  = *(const float4*)&As[kk][ty << 2];
            float4 g4 = *(const float4*)&Bgs[kk][tx << 2];
            float4 u4 = *(const float4*)&Bus[kk][tx << 2];
            float am[4] = {a.x, a.y, a.z, a.w};
            float gn[4] = {g4.x, g4.y, g4.z, g4.w};
            float un[4] = {u4.x, u4.y, u4.z, u4.w};
            #pragma unroll
            for (int mi = 0; mi < 4; mi++)
                #pragma unroll
                for (int ni = 0; ni < 4; ni++) {
                    accg[mi][ni] += am[mi] * gn[ni];
                    accu[mi][ni] += am[mi] * un[ni];
                }
        }
    }

    // epilogue: h = silu(g) * u * combine_weight
    #pragma unroll
    for (int mi = 0; mi < 4; mi++) {
        int srow = (ty << 2) + mi;
        if (slot0 + srow < cnt) {
            int pair = spair[srow];
            float w = g_pairw[pair];
            float* hrow = g_hbuf + (size_t)pair * I_DIM + i0 + (tx << 2);
            #pragma unroll
            for (int ni = 0; ni < 4; ni++) {
                float g = accg[mi][ni];
                float u = accu[mi][ni];
                float sig = 1.0f / (1.0f + expf(-g));
                hrow[ni] = g * sig * u * w;
            }
        }
    }
}

// ---------------------------------------------------------------------------
// Per-expert gathered SGEMM: [slots, I] x Wd[e]^T -> scatter-add into out.
__global__ __launch_bounds__(256) void down_kernel(
    const float* __restrict__ Wd, float* __restrict__ out) {
    int e = blockIdx.z;
    int cnt = g_count[e];
    int slot0 = blockIdx.x * BM;
    if (slot0 >= cnt) return;
    int h0 = blockIdx.y * BN;

    __shared__ float As[BK][BM];
    __shared__ float Bs[BK][BN];
    __shared__ int   spair[BM];

    int tid = threadIdx.x;
    if (tid < BM) {
        int s = slot0 + tid;
        spair[tid] = (s < cnt) ? g_list[e * T + s] : -1;
    }
    __syncthreads();

    int lr = tid >> 2;
    int lk = (tid & 3) << 2;
    int pr = spair[lr];
    const float* arow = g_hbuf + (size_t)((pr >= 0) ? pr : 0) * I_DIM;
    const float* wd = Wd + ((size_t)e * H + h0 + lr) * I_DIM;

    int tx = tid & 15, ty = tid >> 4;
    float acc[4][4];
    #pragma unroll
    for (int i = 0; i < 4; i++)
        #pragma unroll
        for (int j = 0; j < 4; j++) acc[i][j] = 0.0f;

    for (int k0 = 0; k0 < I_DIM; k0 += BK) {
        float4 av = *(const float4*)(arow + k0 + lk);
        float4 bv = *(const float4*)(wd + k0 + lk);
        __syncthreads();
        As[lk + 0][lr] = av.x; As[lk + 1][lr] = av.y;
        As[lk + 2][lr] = av.z; As[lk + 3][lr] = av.w;
        Bs[lk + 0][lr] = bv.x; Bs[lk + 1][lr] = bv.y;
        Bs[lk + 2][lr] = bv.z; Bs[lk + 3][lr] = bv.w;
        __syncthreads();
        #pragma unroll
        for (int kk = 0; kk < BK; kk++) {
            float4 a = *(const float4*)&As[kk][ty << 2];
            float4 b = *(const float4*)&Bs[kk][tx << 2];
            float am[4] = {a.x, a.y, a.z, a.w};
            float bn[4] = {b.x, b.y, b.z, b.w};
            #pragma unroll
            for (int mi = 0; mi < 4; mi++)
                #pragma unroll
                for (int ni = 0; ni < 4; ni++)
                    acc[mi][ni] += am[mi] * bn[ni];
        }
    }

    #pragma unroll
    for (int mi = 0; mi < 4; mi++) {
        int srow = (ty << 2) + mi;
        if (slot0 + srow < cnt) {
            int token = spair[srow] >> 1;
            float* orow = out + (size_t)token * H + h0 + (tx << 2);
            #pragma unroll
            for (int ni = 0; ni < 4; ni++)
                atomicAdd(&orow[ni], acc[mi][ni]);
        }
    }
}

// ---------------------------------------------------------------------------
extern "C" void kernel_launch(void* const* d_in, const int* in_sizes, int n_in,
                              void* d_out, int out_size) {
    const float* x  = (const float*)d_in[0];
    const float* gw = (const float*)d_in[1];
    const float* Wg = (const float*)d_in[2];
    const float* Wu = (const float*)d_in[3];
    const float* Wd = (const float*)d_in[4];
    float* out = (float*)d_out;

    zero_kernel<<<(T * H + 255) / 256, 256>>>(out);
    router_kernel<<<T, 128>>>(x, gw);
    {
        dim3 grid(T / BM, I_DIM / BN, E);
        gateup_kernel<<<grid, 256>>>(x, Wg, Wu);
    }
    {
        dim3 grid(T / BM, H / BN, E);
        down_kernel<<<grid, 256>>>(Wd, out);
    }
}

// round 5
// speedup vs baseline: 2.5907x; 2.5907x over previous
#include <cuda_runtime.h>
#include <cuda_bf16.h>
#include <math.h>

#define T 1024
#define H 2048
#define I_DIM 1024
#define E 32

#define BM 64
#define BK 32
#define PITCH 40   // bf16 elems per smem row: 32 + 8 pad -> conflict-free ldmatrix

// Scratch (no allocations allowed -> __device__ globals)
__device__ int   g_count[E];
__device__ int   g_list[E * 2 * T];      // pair ids (t*2+k) grouped per expert (cap 2T each)
__device__ float g_pairw[T * 2];         // combine weight per (token,k) pair
__device__ float g_hbuf[(size_t)T * 2 * I_DIM];  // silu(g)*u*w, 8 MB

// ---------------------------------------------------------------------------
__global__ void zero_kernel(float* __restrict__ out) {
    int i = blockIdx.x * blockDim.x + threadIdx.x;
    if (i < T * H) out[i] = 0.0f;
    if (i < E) g_count[i] = 0;
}

// ---------------------------------------------------------------------------
__global__ __launch_bounds__(128) void router_kernel(
    const float* __restrict__ x, const float* __restrict__ gw) {
    int t = blockIdx.x;
    __shared__ float logits[E];
    int warp = threadIdx.x >> 5;
    int lane = threadIdx.x & 31;
    const float4* xt = (const float4*)(x + (size_t)t * H);

    for (int e = warp; e < E; e += 4) {
        const float4* w = (const float4*)(gw + (size_t)e * H);
        float s = 0.0f;
        #pragma unroll 4
        for (int h = lane; h < H / 4; h += 32) {
            float4 a = xt[h];
            float4 b = w[h];
            s += a.x * b.x + a.y * b.y + a.z * b.z + a.w * b.w;
        }
        #pragma unroll
        for (int o = 16; o; o >>= 1) s += __shfl_xor_sync(0xffffffffu, s, o);
        if (lane == 0) logits[e] = s;
    }
    __syncthreads();

    if (threadIdx.x == 0) {
        float b1 = -1e30f, b2 = -1e30f;
        int i1 = 0, i2 = 0;
        #pragma unroll
        for (int e = 0; e < E; e++) {
            float v = logits[e];
            if (v > b1)      { b2 = b1; i2 = i1; b1 = v; i1 = e; }
            else if (v > b2) { b2 = v; i2 = e; }
        }
        float w1 = 1.0f / (1.0f + expf(b2 - b1));
        float w2 = 1.0f - w1;
        g_pairw[t * 2 + 0] = w1;
        g_pairw[t * 2 + 1] = w2;
        int p1 = atomicAdd(&g_count[i1], 1);
        g_list[i1 * 2 * T + p1] = t * 2 + 0;
        int p2 = atomicAdd(&g_count[i2], 1);
        g_list[i2 * 2 * T + p2] = t * 2 + 1;
    }
}

// ---------------------------------------------------------------------------
// MMA helpers
__device__ __forceinline__ unsigned smem_u32(const void* p) {
    return (unsigned)__cvta_generic_to_shared(p);
}

__device__ __forceinline__ void ldsm_x4(unsigned addr, unsigned (&r)[4]) {
    asm volatile("ldmatrix.sync.aligned.m8n8.x4.shared.b16 {%0,%1,%2,%3}, [%4];\n"
        : "=r"(r[0]), "=r"(r[1]), "=r"(r[2]), "=r"(r[3]) : "r"(addr));
}

__device__ __forceinline__ void mma16816(float (&c)[4], const unsigned (&a)[4],
                                         unsigned b0, unsigned b1) {
    asm volatile(
        "mma.sync.aligned.m16n8k16.row.col.f32.bf16.bf16.f32 "
        "{%0,%1,%2,%3}, {%4,%5,%6,%7}, {%8,%9}, {%0,%1,%2,%3};\n"
        : "+f"(c[0]), "+f"(c[1]), "+f"(c[2]), "+f"(c[3])
        : "r"(a[0]), "r"(a[1]), "r"(a[2]), "r"(a[3]), "r"(b0), "r"(b1));
}

// split fp32x4 into bf16 hi + bf16 lo (lo = rn(v - hi)); dropped lo*lo ~ 2^-16
__device__ __forceinline__ void split4(float4 v, uint2 &hi, uint2 &lo) {
    __nv_bfloat162 h0 = __float22bfloat162_rn(make_float2(v.x, v.y));
    __nv_bfloat162 h1 = __float22bfloat162_rn(make_float2(v.z, v.w));
    float2 f0 = __bfloat1622float2(h0);
    float2 f1 = __bfloat1622float2(h1);
    __nv_bfloat162 l0 = __float22bfloat162_rn(make_float2(v.x - f0.x, v.y - f0.y));
    __nv_bfloat162 l1 = __float22bfloat162_rn(make_float2(v.z - f1.x, v.w - f1.y));
    hi.x = *reinterpret_cast<unsigned*>(&h0);
    hi.y = *reinterpret_cast<unsigned*>(&h1);
    lo.x = *reinterpret_cast<unsigned*>(&l0);
    lo.y = *reinterpret_cast<unsigned*>(&l1);
}

// ---------------------------------------------------------------------------
// Gate+Up: per-expert gathered GEMM, M=64 slots, N=64 i-cols (g AND u), K=H.
// Tensor-core (mma.sync bf16, split hi/lo, fp32 acc). Fused SwiGLU epilogue.
#define BN_GU 64

__global__ __launch_bounds__(256) void gateup_kernel(
    const float* __restrict__ x,
    const float* __restrict__ Wg,
    const float* __restrict__ Wu) {
    int e = blockIdx.z;
    int cnt = g_count[e];
    int slot0 = blockIdx.x * BM;
    if (slot0 >= cnt) return;
    int i0 = blockIdx.y * BN_GU;

    __shared__ __align__(16) __nv_bfloat16 sAh[BM * PITCH];
    __shared__ __align__(16) __nv_bfloat16 sAl[BM * PITCH];
    __shared__ __align__(16) __nv_bfloat16 sGh[BN_GU * PITCH];
    __shared__ __align__(16) __nv_bfloat16 sGl[BN_GU * PITCH];
    __shared__ __align__(16) __nv_bfloat16 sUh[BN_GU * PITCH];
    __shared__ __align__(16) __nv_bfloat16 sUl[BN_GU * PITCH];
    __shared__ int spair[BM];

    int tid = threadIdx.x;
    if (tid < BM) {
        int s = slot0 + tid;
        spair[tid] = (s < cnt) ? g_list[e * 2 * T + s] : g_list[e * 2 * T];
    }
    __syncthreads();

    // global load mapping: 2 float4 per tile per thread
    int r1 = tid >> 3;            // 0..31
    int c4 = (tid & 7) << 2;      // 0,4,...,28
    int r2 = r1 + 32;
    const float* a1 = x + (size_t)(spair[r1] >> 1) * H + c4;
    const float* a2 = x + (size_t)(spair[r2] >> 1) * H + c4;
    const float* gp1 = Wg + ((size_t)e * I_DIM + i0 + r1) * H + c4;
    const float* gp2 = gp1 + (size_t)32 * H;
    const float* up1 = Wu + ((size_t)e * I_DIM + i0 + r1) * H + c4;
    const float* up2 = up1 + (size_t)32 * H;
    int off1 = r1 * PITCH + c4;
    int off2 = r2 * PITCH + c4;

    int warp = tid >> 5, lane = tid & 31;
    int wm = warp >> 2;           // 0..1  (32 rows each)
    int wn = warp & 3;            // 0..3  (16 cols each)

    unsigned uAh = smem_u32(sAh), uAl = smem_u32(sAl);
    unsigned uGh = smem_u32(sGh), uGl = smem_u32(sGl);
    unsigned uUh = smem_u32(sUh), uUl = smem_u32(sUl);

    unsigned aoff0 = ((wm * 32 + (lane & 15)) * PITCH + (lane >> 4) * 8) * 2;
    unsigned aoff1 = aoff0 + 16 * PITCH * 2;
    unsigned boff  = ((wn * 16 + (lane & 7) + ((lane >> 4) & 1) * 8) * PITCH
                      + ((lane >> 3) & 1) * 8) * 2;

    float cg[2][2][4] = {};
    float cu[2][2][4] = {};

    for (int k0 = 0; k0 < H; k0 += BK) {
        float4 va1 = *(const float4*)(a1 + k0);
        float4 va2 = *(const float4*)(a2 + k0);
        float4 vg1 = *(const float4*)(gp1 + k0);
        float4 vg2 = *(const float4*)(gp2 + k0);
        float4 vu1 = *(const float4*)(up1 + k0);
        float4 vu2 = *(const float4*)(up2 + k0);
        __syncthreads();
        uint2 h, l;
        split4(va1, h, l); *(uint2*)&sAh[off1] = h; *(uint2*)&sAl[off1] = l;
        split4(va2, h, l); *(uint2*)&sAh[off2] = h; *(uint2*)&sAl[off2] = l;
        split4(vg1, h, l); *(uint2*)&sGh[off1] = h; *(uint2*)&sGl[off1] = l;
        split4(vg2, h, l); *(uint2*)&sGh[off2] = h; *(uint2*)&sGl[off2] = l;
        split4(vu1, h, l); *(uint2*)&sUh[off1] = h; *(uint2*)&sUl[off1] = l;
        split4(vu2, h, l); *(uint2*)&sUh[off2] = h; *(uint2*)&sUl[off2] = l;
        __syncthreads();

        #pragma unroll
        for (int ks = 0; ks < 2; ks++) {
            unsigned kb = ks * 32;   // 16 halves = 32 bytes
            unsigned ah0[4], ah1[4], al0[4], al1[4];
            ldsm_x4(uAh + aoff0 + kb, ah0);
            ldsm_x4(uAh + aoff1 + kb, ah1);
            ldsm_x4(uAl + aoff0 + kb, al0);
            ldsm_x4(uAl + aoff1 + kb, al1);
            unsigned bgh[4], bgl[4], buh[4], bul[4];
            ldsm_x4(uGh + boff + kb, bgh);
            ldsm_x4(uGl + boff + kb, bgl);
            ldsm_x4(uUh + boff + kb, buh);
            ldsm_x4(uUl + boff + kb, bul);

            // gate
            mma16816(cg[0][0], ah0, bgh[0], bgh[1]);
            mma16816(cg[0][0], ah0, bgl[0], bgl[1]);
            mma16816(cg[0][0], al0, bgh[0], bgh[1]);
            mma16816(cg[0][1], ah0, bgh[2], bgh[3]);
            mma16816(cg[0][1], ah0, bgl[2], bgl[3]);
            mma16816(cg[0][1], al0, bgh[2], bgh[3]);
            mma16816(cg[1][0], ah1, bgh[0], bgh[1]);
            mma16816(cg[1][0], ah1, bgl[0], bgl[1]);
            mma16816(cg[1][0], al1, bgh[0], bgh[1]);
            mma16816(cg[1][1], ah1, bgh[2], bgh[3]);
            mma16816(cg[1][1], ah1, bgl[2], bgl[3]);
            mma16816(cg[1][1], al1, bgh[2], bgh[3]);
            // up
            mma16816(cu[0][0], ah0, buh[0], buh[1]);
            mma16816(cu[0][0], ah0, bul[0], bul[1]);
            mma16816(cu[0][0], al0, buh[0], buh[1]);
            mma16816(cu[0][1], ah0, buh[2], buh[3]);
            mma16816(cu[0][1], ah0, bul[2], bul[3]);
            mma16816(cu[0][1], al0, buh[2], buh[3]);
            mma16816(cu[1][0], ah1, buh[0], buh[1]);
            mma16816(cu[1][0], ah1, bul[0], bul[1]);
            mma16816(cu[1][0], al1, buh[0], buh[1]);
            mma16816(cu[1][1], ah1, buh[2], buh[3]);
            mma16816(cu[1][1], ah1, bul[2], bul[3]);
            mma16816(cu[1][1], al1, buh[2], buh[3]);
        }
    }

    // epilogue: h = silu(g) * u * combine_weight -> g_hbuf[pair][i]
    #pragma unroll
    for (int mi = 0; mi < 2; mi++) {
        #pragma unroll
        for (int half = 0; half < 2; half++) {
            int row = wm * 32 + mi * 16 + (lane >> 2) + half * 8;
            if (slot0 + row < cnt) {
                int pair = spair[row];
                float w = g_pairw[pair];
                float* hrow = g_hbuf + (size_t)pair * I_DIM + i0 + wn * 16;
                #pragma unroll
                for (int ni = 0; ni < 2; ni++) {
                    int col = ni * 8 + ((lane & 3) << 1);
                    float g0 = cg[mi][ni][half * 2 + 0];
                    float g1 = cg[mi][ni][half * 2 + 1];
                    float u0 = cu[mi][ni][half * 2 + 0];
                    float u1 = cu[mi][ni][half * 2 + 1];
                    hrow[col]     = g0 / (1.0f + expf(-g0)) * u0 * w;
                    hrow[col + 1] = g1 / (1.0f + expf(-g1)) * u1 * w;
                }
            }
        }
    }
}

// ---------------------------------------------------------------------------
// Down: per-expert gathered GEMM, M=64 slots, N=128 h-cols, K=I. Scatter-add.
#define BN_D 128

__global__ __launch_bounds__(256) void down_kernel(
    const float* __restrict__ Wd, float* __restrict__ out) {
    int e = blockIdx.z;
    int cnt = g_count[e];
    int slot0 = blockIdx.x * BM;
    if (slot0 >= cnt) return;
    int h0 = blockIdx.y * BN_D;

    __shared__ __align__(16) __nv_bfloat16 sAh[BM * PITCH];
    __shared__ __align__(16) __nv_bfloat16 sAl[BM * PITCH];
    __shared__ __align__(16) __nv_bfloat16 sBh[BN_D * PITCH];
    __shared__ __align__(16) __nv_bfloat16 sBl[BN_D * PITCH];
    __shared__ int spair[BM];

    int tid = threadIdx.x;
    if (tid < BM) {
        int s = slot0 + tid;
        spair[tid] = (s < cnt) ? g_list[e * 2 * T + s] : g_list[e * 2 * T];
    }
    __syncthreads();

    int r1 = tid >> 3;
    int c4 = (tid & 7) << 2;
    int r2 = r1 + 32;
    const float* a1 = g_hbuf + (size_t)spair[r1] * I_DIM + c4;
    const float* a2 = g_hbuf + (size_t)spair[r2] * I_DIM + c4;
    const float* b1 = Wd + ((size_t)e * H + h0 + r1) * I_DIM + c4;
    const float* b2 = b1 + (size_t)32 * I_DIM;
    const float* b3 = b1 + (size_t)64 * I_DIM;
    const float* b4 = b1 + (size_t)96 * I_DIM;
    int offA1 = r1 * PITCH + c4;
    int offA2 = r2 * PITCH + c4;

    int warp = tid >> 5, lane = tid & 31;
    int wm = warp >> 2;           // 0..1
    int wn = warp & 3;            // 0..3 (32 cols each)

    unsigned uAh = smem_u32(sAh), uAl = smem_u32(sAl);
    unsigned uBh = smem_u32(sBh), uBl = smem_u32(sBl);

    unsigned aoff0 = ((wm * 32 + (lane & 15)) * PITCH + (lane >> 4) * 8) * 2;
    unsigned aoff1 = aoff0 + 16 * PITCH * 2;
    unsigned boffbase = ((wn * 32 + (lane & 7) + ((lane >> 4) & 1) * 8) * PITCH
                         + ((lane >> 3) & 1) * 8) * 2;

    float c[2][4][4] = {};

    for (int k0 = 0; k0 < I_DIM; k0 += BK) {
        float4 va1 = *(const float4*)(a1 + k0);
        float4 va2 = *(const float4*)(a2 + k0);
        float4 vb1 = *(const float4*)(b1 + k0);
        float4 vb2 = *(const float4*)(b2 + k0);
        float4 vb3 = *(const float4*)(b3 + k0);
        float4 vb4 = *(const float4*)(b4 + k0);
        __syncthreads();
        uint2 h, l;
        split4(va1, h, l); *(uint2*)&sAh[offA1] = h; *(uint2*)&sAl[offA1] = l;
        split4(va2, h, l); *(uint2*)&sAh[offA2] = h; *(uint2*)&sAl[offA2] = l;
        split4(vb1, h, l); *(uint2*)&sBh[offA1] = h; *(uint2*)&sBl[offA1] = l;
        split4(vb2, h, l); *(uint2*)&sBh[offA2] = h; *(uint2*)&sBl[offA2] = l;
        split4(vb3, h, l);
        *(uint2*)&sBh[offA1 + 64 * PITCH] = h; *(uint2*)&sBl[offA1 + 64 * PITCH] = l;
        split4(vb4, h, l);
        *(uint2*)&sBh[offA2 + 64 * PITCH] = h; *(uint2*)&sBl[offA2 + 64 * PITCH] = l;
        __syncthreads();

        #pragma unroll
        for (int ks = 0; ks < 2; ks++) {
            unsigned kb = ks * 32;
            unsigned ah0[4], ah1[4], al0[4], al1[4];
            ldsm_x4(uAh + aoff0 + kb, ah0);
            ldsm_x4(uAh + aoff1 + kb, ah1);
            ldsm_x4(uAl + aoff0 + kb, al0);
            ldsm_x4(uAl + aoff1 + kb, al1);
            unsigned bh0[4], bh1[4], bl0[4], bl1[4];
            ldsm_x4(uBh + boffbase + kb, bh0);
            ldsm_x4(uBh + boffbase + 16 * PITCH * 2 + kb, bh1);
            ldsm_x4(uBl + boffbase + kb, bl0);
            ldsm_x4(uBl + boffbase + 16 * PITCH * 2 + kb, bl1);

            #pragma unroll
            for (int mi = 0; mi < 2; mi++) {
                const unsigned (&ah)[4] = mi ? ah1 : ah0;
                const unsigned (&al)[4] = mi ? al1 : al0;
                mma16816(c[mi][0], ah, bh0[0], bh0[1]);
                mma16816(c[mi][0], ah, bl0[0], bl0[1]);
                mma16816(c[mi][0], al, bh0[0], bh0[1]);
                mma16816(c[mi][1], ah, bh0[2], bh0[3]);
                mma16816(c[mi][1], ah, bl0[2], bl0[3]);
                mma16816(c[mi][1], al, bh0[2], bh0[3]);
                mma16816(c[mi][2], ah, bh1[0], bh1[1]);
                mma16816(c[mi][2], ah, bl1[0], bl1[1]);
                mma16816(c[mi][2], al, bh1[0], bh1[1]);
                mma16816(c[mi][3], ah, bh1[2], bh1[3]);
                mma16816(c[mi][3], ah, bl1[2], bl1[3]);
                mma16816(c[mi][3], al, bh1[2], bh1[3]);
            }
        }
    }

    // epilogue: scatter-add into out[token][h]
    #pragma unroll
    for (int mi = 0; mi < 2; mi++) {
        #pragma unroll
        for (int half = 0; half < 2; half++) {
            int row = wm * 32 + mi * 16 + (lane >> 2) + half * 8;
            if (slot0 + row < cnt) {
                int token = spair[row] >> 1;
                float* orow = out + (size_t)token * H + h0 + wn * 32;
                #pragma unroll
                for (int ni = 0; ni < 4; ni++) {
                    int col = ni * 8 + ((lane & 3) << 1);
                    atomicAdd(&orow[col],     c[mi][ni][half * 2 + 0]);
                    atomicAdd(&orow[col + 1], c[mi][ni][half * 2 + 1]);
                }
            }
        }
    }
}

// ---------------------------------------------------------------------------
extern "C" void kernel_launch(void* const* d_in, const int* in_sizes, int n_in,
                              void* d_out, int out_size) {
    const float* x  = (const float*)d_in[0];
    const float* gw = (const float*)d_in[1];
    const float* Wg = (const float*)d_in[2];
    const float* Wu = (const float*)d_in[3];
    const float* Wd = (const float*)d_in[4];
    float* out = (float*)d_out;

    zero_kernel<<<(T * H + 255) / 256, 256>>>(out);
    router_kernel<<<T, 128>>>(x, gw);
    {
        dim3 grid(T * 2 / BM, I_DIM / BN_GU, E);   // per-expert worst case 2T slots
        gateup_kernel<<<grid, 256>>>(x, Wg, Wu);
    }
    {
        dim3 grid(T * 2 / BM, H / BN_D, E);
        down_kernel<<<grid, 256>>>(Wd, out);
    }
}

// round 6
// speedup vs baseline: 2.6525x; 1.0239x over previous
#include <cuda_runtime.h>
#include <cuda_bf16.h>
#include <math.h>

#define T 1024
#define H 2048
#define I_DIM 1024
#define E 32

#define BM 64
#define BK 32
#define PITCH 40   // bf16 elems per smem row: 32 + 8 pad -> conflict-free ldmatrix

// Scratch (no allocations allowed -> __device__ globals)
__device__ int   g_count[E];
__device__ int   g_list[E * 2 * T];      // pair ids (t*2+k) grouped per expert (cap 2T each)
__device__ float g_pairw[T * 2];         // combine weight per (token,k) pair
__device__ float g_hbuf[(size_t)T * 2 * I_DIM];  // silu(g)*u*w, 8 MB

// ---------------------------------------------------------------------------
__global__ void zero_kernel(float* __restrict__ out) {
    int i = blockIdx.x * blockDim.x + threadIdx.x;
    if (i < T * H) out[i] = 0.0f;
    if (i < E) g_count[i] = 0;
}

// ---------------------------------------------------------------------------
__global__ __launch_bounds__(128) void router_kernel(
    const float* __restrict__ x, const float* __restrict__ gw) {
    int t = blockIdx.x;
    __shared__ float logits[E];
    int warp = threadIdx.x >> 5;
    int lane = threadIdx.x & 31;
    const float4* xt = (const float4*)(x + (size_t)t * H);

    for (int e = warp; e < E; e += 4) {
        const float4* w = (const float4*)(gw + (size_t)e * H);
        float s = 0.0f;
        #pragma unroll 4
        for (int h = lane; h < H / 4; h += 32) {
            float4 a = xt[h];
            float4 b = w[h];
            s += a.x * b.x + a.y * b.y + a.z * b.z + a.w * b.w;
        }
        #pragma unroll
        for (int o = 16; o; o >>= 1) s += __shfl_xor_sync(0xffffffffu, s, o);
        if (lane == 0) logits[e] = s;
    }
    __syncthreads();

    if (threadIdx.x == 0) {
        float b1 = -1e30f, b2 = -1e30f;
        int i1 = 0, i2 = 0;
        #pragma unroll
        for (int e = 0; e < E; e++) {
            float v = logits[e];
            if (v > b1)      { b2 = b1; i2 = i1; b1 = v; i1 = e; }
            else if (v > b2) { b2 = v; i2 = e; }
        }
        float w1 = 1.0f / (1.0f + expf(b2 - b1));
        float w2 = 1.0f - w1;
        g_pairw[t * 2 + 0] = w1;
        g_pairw[t * 2 + 1] = w2;
        int p1 = atomicAdd(&g_count[i1], 1);
        g_list[i1 * 2 * T + p1] = t * 2 + 0;
        int p2 = atomicAdd(&g_count[i2], 1);
        g_list[i2 * 2 * T + p2] = t * 2 + 1;
    }
}

// ---------------------------------------------------------------------------
// MMA helpers
__device__ __forceinline__ unsigned smem_u32(const void* p) {
    return (unsigned)__cvta_generic_to_shared(p);
}

__device__ __forceinline__ void ldsm_x4(unsigned addr, unsigned (&r)[4]) {
    asm volatile("ldmatrix.sync.aligned.m8n8.x4.shared.b16 {%0,%1,%2,%3}, [%4];\n"
        : "=r"(r[0]), "=r"(r[1]), "=r"(r[2]), "=r"(r[3]) : "r"(addr));
}

__device__ __forceinline__ void mma16816(float (&c)[4], const unsigned (&a)[4],
                                         unsigned b0, unsigned b1) {
    asm volatile(
        "mma.sync.aligned.m16n8k16.row.col.f32.bf16.bf16.f32 "
        "{%0,%1,%2,%3}, {%4,%5,%6,%7}, {%8,%9}, {%0,%1,%2,%3};\n"
        : "+f"(c[0]), "+f"(c[1]), "+f"(c[2]), "+f"(c[3])
        : "r"(a[0]), "r"(a[1]), "r"(a[2]), "r"(a[3]), "r"(b0), "r"(b1));
}

// split fp32x4 into bf16 hi + bf16 lo (lo = rn(v - hi)); dropped lo*lo ~ 2^-16
__device__ __forceinline__ void split4(float4 v, uint2 &hi, uint2 &lo) {
    __nv_bfloat162 h0 = __float22bfloat162_rn(make_float2(v.x, v.y));
    __nv_bfloat162 h1 = __float22bfloat162_rn(make_float2(v.z, v.w));
    float2 f0 = __bfloat1622float2(h0);
    float2 f1 = __bfloat1622float2(h1);
    __nv_bfloat162 l0 = __float22bfloat162_rn(make_float2(v.x - f0.x, v.y - f0.y));
    __nv_bfloat162 l1 = __float22bfloat162_rn(make_float2(v.z - f1.x, v.w - f1.y));
    hi.x = *reinterpret_cast<unsigned*>(&h0);
    hi.y = *reinterpret_cast<unsigned*>(&h1);
    lo.x = *reinterpret_cast<unsigned*>(&l0);
    lo.y = *reinterpret_cast<unsigned*>(&l1);
}

// ---------------------------------------------------------------------------
// Gate+Up: per-expert gathered GEMM, M=64 slots, N=64 i-cols (g AND u), K=H.
// Software-pipelined: next-iter LDG issued right after STS frees the regs,
// so global latency overlaps the MMA phase.
#define BN_GU 64

__global__ __launch_bounds__(256) void gateup_kernel(
    const float* __restrict__ x,
    const float* __restrict__ Wg,
    const float* __restrict__ Wu) {
    int e = blockIdx.z;
    int cnt = g_count[e];
    int slot0 = blockIdx.x * BM;
    if (slot0 >= cnt) return;
    int i0 = blockIdx.y * BN_GU;

    __shared__ __align__(16) __nv_bfloat16 sAh[BM * PITCH];
    __shared__ __align__(16) __nv_bfloat16 sAl[BM * PITCH];
    __shared__ __align__(16) __nv_bfloat16 sGh[BN_GU * PITCH];
    __shared__ __align__(16) __nv_bfloat16 sGl[BN_GU * PITCH];
    __shared__ __align__(16) __nv_bfloat16 sUh[BN_GU * PITCH];
    __shared__ __align__(16) __nv_bfloat16 sUl[BN_GU * PITCH];
    __shared__ int spair[BM];

    int tid = threadIdx.x;
    if (tid < BM) {
        int s = slot0 + tid;
        spair[tid] = (s < cnt) ? g_list[e * 2 * T + s] : g_list[e * 2 * T];
    }
    __syncthreads();

    // global load mapping: 2 float4 per tile per thread
    int r1 = tid >> 3;            // 0..31
    int c4 = (tid & 7) << 2;      // 0,4,...,28
    int r2 = r1 + 32;
    const float* a1 = x + (size_t)(spair[r1] >> 1) * H + c4;
    const float* a2 = x + (size_t)(spair[r2] >> 1) * H + c4;
    const float* gp1 = Wg + ((size_t)e * I_DIM + i0 + r1) * H + c4;
    const float* gp2 = gp1 + (size_t)32 * H;
    const float* up1 = Wu + ((size_t)e * I_DIM + i0 + r1) * H + c4;
    const float* up2 = up1 + (size_t)32 * H;
    int off1 = r1 * PITCH + c4;
    int off2 = r2 * PITCH + c4;

    int warp = tid >> 5, lane = tid & 31;
    int wm = warp >> 2;           // 0..1  (32 rows each)
    int wn = warp & 3;            // 0..3  (16 cols each)

    unsigned uAh = smem_u32(sAh), uAl = smem_u32(sAl);
    unsigned uGh = smem_u32(sGh), uGl = smem_u32(sGl);
    unsigned uUh = smem_u32(sUh), uUl = smem_u32(sUl);

    unsigned aoff0 = ((wm * 32 + (lane & 15)) * PITCH + (lane >> 4) * 8) * 2;
    unsigned aoff1 = aoff0 + 16 * PITCH * 2;
    unsigned boff  = ((wn * 16 + (lane & 7) + ((lane >> 4) & 1) * 8) * PITCH
                      + ((lane >> 3) & 1) * 8) * 2;

    float cg[2][2][4] = {};
    float cu[2][2][4] = {};

    // prologue: load k0 = 0
    float4 va1 = *(const float4*)(a1);
    float4 va2 = *(const float4*)(a2);
    float4 vg1 = *(const float4*)(gp1);
    float4 vg2 = *(const float4*)(gp2);
    float4 vu1 = *(const float4*)(up1);
    float4 vu2 = *(const float4*)(up2);

    for (int k0 = 0; k0 < H; k0 += BK) {
        __syncthreads();
        uint2 h, l;
        split4(va1, h, l); *(uint2*)&sAh[off1] = h; *(uint2*)&sAl[off1] = l;
        split4(va2, h, l); *(uint2*)&sAh[off2] = h; *(uint2*)&sAl[off2] = l;
        split4(vg1, h, l); *(uint2*)&sGh[off1] = h; *(uint2*)&sGl[off1] = l;
        split4(vg2, h, l); *(uint2*)&sGh[off2] = h; *(uint2*)&sGl[off2] = l;
        split4(vu1, h, l); *(uint2*)&sUh[off1] = h; *(uint2*)&sUl[off1] = l;
        split4(vu2, h, l); *(uint2*)&sUh[off2] = h; *(uint2*)&sUl[off2] = l;
        __syncthreads();

        // issue next-iteration loads: latency hides behind the MMA phase below
        int kn = k0 + BK;
        if (kn < H) {
            va1 = *(const float4*)(a1 + kn);
            va2 = *(const float4*)(a2 + kn);
            vg1 = *(const float4*)(gp1 + kn);
            vg2 = *(const float4*)(gp2 + kn);
            vu1 = *(const float4*)(up1 + kn);
            vu2 = *(const float4*)(up2 + kn);
        }

        #pragma unroll
        for (int ks = 0; ks < 2; ks++) {
            unsigned kb = ks * 32;   // 16 halves = 32 bytes
            unsigned ah0[4], ah1[4], al0[4], al1[4];
            ldsm_x4(uAh + aoff0 + kb, ah0);
            ldsm_x4(uAh + aoff1 + kb, ah1);
            ldsm_x4(uAl + aoff0 + kb, al0);
            ldsm_x4(uAl + aoff1 + kb, al1);
            unsigned bgh[4], bgl[4], buh[4], bul[4];
            ldsm_x4(uGh + boff + kb, bgh);
            ldsm_x4(uGl + boff + kb, bgl);
            ldsm_x4(uUh + boff + kb, buh);
            ldsm_x4(uUl + boff + kb, bul);

            // gate
            mma16816(cg[0][0], ah0, bgh[0], bgh[1]);
            mma16816(cg[0][0], ah0, bgl[0], bgl[1]);
            mma16816(cg[0][0], al0, bgh[0], bgh[1]);
            mma16816(cg[0][1], ah0, bgh[2], bgh[3]);
            mma16816(cg[0][1], ah0, bgl[2], bgl[3]);
            mma16816(cg[0][1], al0, bgh[2], bgh[3]);
            mma16816(cg[1][0], ah1, bgh[0], bgh[1]);
            mma16816(cg[1][0], ah1, bgl[0], bgl[1]);
            mma16816(cg[1][0], al1, bgh[0], bgh[1]);
            mma16816(cg[1][1], ah1, bgh[2], bgh[3]);
            mma16816(cg[1][1], ah1, bgl[2], bgl[3]);
            mma16816(cg[1][1], al1, bgh[2], bgh[3]);
            // up
            mma16816(cu[0][0], ah0, buh[0], buh[1]);
            mma16816(cu[0][0], ah0, bul[0], bul[1]);
            mma16816(cu[0][0], al0, buh[0], buh[1]);
            mma16816(cu[0][1], ah0, buh[2], buh[3]);
            mma16816(cu[0][1], ah0, bul[2], bul[3]);
            mma16816(cu[0][1], al0, buh[2], buh[3]);
            mma16816(cu[1][0], ah1, buh[0], buh[1]);
            mma16816(cu[1][0], ah1, bul[0], bul[1]);
            mma16816(cu[1][0], al1, buh[0], buh[1]);
            mma16816(cu[1][1], ah1, buh[2], buh[3]);
            mma16816(cu[1][1], ah1, bul[2], bul[3]);
            mma16816(cu[1][1], al1, buh[2], buh[3]);
        }
    }

    // epilogue: h = silu(g) * u * combine_weight -> g_hbuf[pair][i]
    #pragma unroll
    for (int mi = 0; mi < 2; mi++) {
        #pragma unroll
        for (int half = 0; half < 2; half++) {
            int row = wm * 32 + mi * 16 + (lane >> 2) + half * 8;
            if (slot0 + row < cnt) {
                int pair = spair[row];
                float w = g_pairw[pair];
                float* hrow = g_hbuf + (size_t)pair * I_DIM + i0 + wn * 16;
                #pragma unroll
                for (int ni = 0; ni < 2; ni++) {
                    int col = ni * 8 + ((lane & 3) << 1);
                    float g0 = cg[mi][ni][half * 2 + 0];
                    float g1 = cg[mi][ni][half * 2 + 1];
                    float u0 = cu[mi][ni][half * 2 + 0];
                    float u1 = cu[mi][ni][half * 2 + 1];
                    hrow[col]     = g0 / (1.0f + expf(-g0)) * u0 * w;
                    hrow[col + 1] = g1 / (1.0f + expf(-g1)) * u1 * w;
                }
            }
        }
    }
}

// ---------------------------------------------------------------------------
// Down: per-expert gathered GEMM, M=64 slots, N=128 h-cols, K=I. Scatter-add.
// Same software pipeline as gateup.
#define BN_D 128

__global__ __launch_bounds__(256) void down_kernel(
    const float* __restrict__ Wd, float* __restrict__ out) {
    int e = blockIdx.z;
    int cnt = g_count[e];
    int slot0 = blockIdx.x * BM;
    if (slot0 >= cnt) return;
    int h0 = blockIdx.y * BN_D;

    __shared__ __align__(16) __nv_bfloat16 sAh[BM * PITCH];
    __shared__ __align__(16) __nv_bfloat16 sAl[BM * PITCH];
    __shared__ __align__(16) __nv_bfloat16 sBh[BN_D * PITCH];
    __shared__ __align__(16) __nv_bfloat16 sBl[BN_D * PITCH];
    __shared__ int spair[BM];

    int tid = threadIdx.x;
    if (tid < BM) {
        int s = slot0 + tid;
        spair[tid] = (s < cnt) ? g_list[e * 2 * T + s] : g_list[e * 2 * T];
    }
    __syncthreads();

    int r1 = tid >> 3;
    int c4 = (tid & 7) << 2;
    int r2 = r1 + 32;
    const float* a1 = g_hbuf + (size_t)spair[r1] * I_DIM + c4;
    const float* a2 = g_hbuf + (size_t)spair[r2] * I_DIM + c4;
    const float* b1 = Wd + ((size_t)e * H + h0 + r1) * I_DIM + c4;
    const float* b2 = b1 + (size_t)32 * I_DIM;
    const float* b3 = b1 + (size_t)64 * I_DIM;
    const float* b4 = b1 + (size_t)96 * I_DIM;
    int offA1 = r1 * PITCH + c4;
    int offA2 = r2 * PITCH + c4;

    int warp = tid >> 5, lane = tid & 31;
    int wm = warp >> 2;           // 0..1
    int wn = warp & 3;            // 0..3 (32 cols each)

    unsigned uAh = smem_u32(sAh), uAl = smem_u32(sAl);
    unsigned uBh = smem_u32(sBh), uBl = smem_u32(sBl);

    unsigned aoff0 = ((wm * 32 + (lane & 15)) * PITCH + (lane >> 4) * 8) * 2;
    unsigned aoff1 = aoff0 + 16 * PITCH * 2;
    unsigned boffbase = ((wn * 32 + (lane & 7) + ((lane >> 4) & 1) * 8) * PITCH
                         + ((lane >> 3) & 1) * 8) * 2;

    float c[2][4][4] = {};

    // prologue loads
    float4 va1 = *(const float4*)(a1);
    float4 va2 = *(const float4*)(a2);
    float4 vb1 = *(const float4*)(b1);
    float4 vb2 = *(const float4*)(b2);
    float4 vb3 = *(const float4*)(b3);
    float4 vb4 = *(const float4*)(b4);

    for (int k0 = 0; k0 < I_DIM; k0 += BK) {
        __syncthreads();
        uint2 h, l;
        split4(va1, h, l); *(uint2*)&sAh[offA1] = h; *(uint2*)&sAl[offA1] = l;
        split4(va2, h, l); *(uint2*)&sAh[offA2] = h; *(uint2*)&sAl[offA2] = l;
        split4(vb1, h, l); *(uint2*)&sBh[offA1] = h; *(uint2*)&sBl[offA1] = l;
        split4(vb2, h, l); *(uint2*)&sBh[offA2] = h; *(uint2*)&sBl[offA2] = l;
        split4(vb3, h, l);
        *(uint2*)&sBh[offA1 + 64 * PITCH] = h; *(uint2*)&sBl[offA1 + 64 * PITCH] = l;
        split4(vb4, h, l);
        *(uint2*)&sBh[offA2 + 64 * PITCH] = h; *(uint2*)&sBl[offA2 + 64 * PITCH] = l;
        __syncthreads();

        // issue next-iteration loads before the MMA phase
        int kn = k0 + BK;
        if (kn < I_DIM) {
            va1 = *(const float4*)(a1 + kn);
            va2 = *(const float4*)(a2 + kn);
            vb1 = *(const float4*)(b1 + kn);
            vb2 = *(const float4*)(b2 + kn);
            vb3 = *(const float4*)(b3 + kn);
            vb4 = *(const float4*)(b4 + kn);
        }

        #pragma unroll
        for (int ks = 0; ks < 2; ks++) {
            unsigned kb = ks * 32;
            unsigned ah0[4], ah1[4], al0[4], al1[4];
            ldsm_x4(uAh + aoff0 + kb, ah0);
            ldsm_x4(uAh + aoff1 + kb, ah1);
            ldsm_x4(uAl + aoff0 + kb, al0);
            ldsm_x4(uAl + aoff1 + kb, al1);
            unsigned bh0[4], bh1[4], bl0[4], bl1[4];
            ldsm_x4(uBh + boffbase + kb, bh0);
            ldsm_x4(uBh + boffbase + 16 * PITCH * 2 + kb, bh1);
            ldsm_x4(uBl + boffbase + kb, bl0);
            ldsm_x4(uBl + boffbase + 16 * PITCH * 2 + kb, bl1);

            #pragma unroll
            for (int mi = 0; mi < 2; mi++) {
                const unsigned (&ah)[4] = mi ? ah1 : ah0;
                const unsigned (&al)[4] = mi ? al1 : al0;
                mma16816(c[mi][0], ah, bh0[0], bh0[1]);
                mma16816(c[mi][0], ah, bl0[0], bl0[1]);
                mma16816(c[mi][0], al, bh0[0], bh0[1]);
                mma16816(c[mi][1], ah, bh0[2], bh0[3]);
                mma16816(c[mi][1], ah, bl0[2], bl0[3]);
                mma16816(c[mi][1], al, bh0[2], bh0[3]);
                mma16816(c[mi][2], ah, bh1[0], bh1[1]);
                mma16816(c[mi][2], ah, bl1[0], bl1[1]);
                mma16816(c[mi][2], al, bh1[0], bh1[1]);
                mma16816(c[mi][3], ah, bh1[2], bh1[3]);
                mma16816(c[mi][3], ah, bl1[2], bl1[3]);
                mma16816(c[mi][3], al, bh1[2], bh1[3]);
            }
        }
    }

    // epilogue: scatter-add into out[token][h]
    #pragma unroll
    for (int mi = 0; mi < 2; mi++) {
        #pragma unroll
        for (int half = 0; half < 2; half++) {
            int row = wm * 32 + mi * 16 + (lane >> 2) + half * 8;
            if (slot0 + row < cnt) {
                int token = spair[row] >> 1;
                float* orow = out + (size_t)token * H + h0 + wn * 32;
                #pragma unroll
                for (int ni = 0; ni < 4; ni++) {
                    int col = ni * 8 + ((lane & 3) << 1);
                    atomicAdd(&orow[col],     c[mi][ni][half * 2 + 0]);
                    atomicAdd(&orow[col + 1], c[mi][ni][half * 2 + 1]);
                }
            }
        }
    }
}

// ---------------------------------------------------------------------------
extern "C" void kernel_launch(void* const* d_in, const int* in_sizes, int n_in,
                              void* d_out, int out_size) {
    const float* x  = (const float*)d_in[0];
    const float* gw = (const float*)d_in[1];
    const float* Wg = (const float*)d_in[2];
    const float* Wu = (const float*)d_in[3];
    const float* Wd = (const float*)d_in[4];
    float* out = (float*)d_out;

    zero_kernel<<<(T * H + 255) / 256, 256>>>(out);
    router_kernel<<<T, 128>>>(x, gw);
    {
        dim3 grid(T * 2 / BM, I_DIM / BN_GU, E);   // per-expert worst case 2T slots
        gateup_kernel<<<grid, 256>>>(x, Wg, Wu);
    }
    {
        dim3 grid(T * 2 / BM, H / BN_D, E);
        down_kernel<<<grid, 256>>>(Wd, out);
    }
}